// round 3
// baseline (speedup 1.0000x reference)
#include <cuda_runtime.h>

// Problem constants
#define B_  256
#define T_  100
#define I_  2048
#define H_  2048
#define M_  (B_ * T_)   // 25600 GEMM rows

#define BM 128
#define BN 128
#define BK 16
#define TM 8
#define TN 4
#define NTHREADS 512
#define LDS 132   // padded smem row stride (floats), multiple of 4

// proj scratch: [M_, H_] fp32 = 200 MiB (device global, not an allocation)
__device__ float g_proj[(size_t)M_ * H_];

// ---------------------------------------------------------------------------
// Kernel A: proj = X @ W^T + bias, computed with error-free transformations
// (Dot2 / Ogita-Rump-Oishi): result is as if accumulated in ~fp64 and rounded
// once. TwoProd via FMA captures the product rounding; TwoSum captures the
// accumulation rounding; both feed a compensation register.
// ---------------------------------------------------------------------------
__global__ __launch_bounds__(NTHREADS, 1)
void lif_gemm_eft_kernel(const float* __restrict__ X,
                         const float* __restrict__ W,
                         const float* __restrict__ bias,
                         float* __restrict__ proj)
{
    __shared__ float As[BK * LDS];   // [k][m]
    __shared__ float Bs[BK * LDS];   // [k][n]

    const int bx = blockIdx.x;   // N tile (over H)
    const int by = blockIdx.y;   // M tile (over B*T)
    const int tid = threadIdx.x; // 0..511
    const int tx = tid & 31;     // 0..31 -> N (TN=4 each)
    const int ty = tid >> 5;     // 0..15 -> M (TM=8 each)

    const float* Xp = X + (size_t)by * BM * I_;
    const float* Wp = W + (size_t)bx * BN * I_;

    float s[TM][TN];   // primary sums
    float c[TM][TN];   // compensation
    #pragma unroll
    for (int i = 0; i < TM; i++)
        #pragma unroll
        for (int j = 0; j < TN; j++) { s[i][j] = 0.0f; c[i][j] = 0.0f; }

    for (int k0 = 0; k0 < I_; k0 += BK) {
        // Load 128x16 tiles: 512 float4 per tile, 1 per thread per tile.
        {
            int row  = tid >> 2;        // 0..127
            int col4 = tid & 3;         // 0..3
            float4 va = *(const float4*)(Xp + (size_t)row * I_ + k0 + col4 * 4);
            As[(col4 * 4 + 0) * LDS + row] = va.x;
            As[(col4 * 4 + 1) * LDS + row] = va.y;
            As[(col4 * 4 + 2) * LDS + row] = va.z;
            As[(col4 * 4 + 3) * LDS + row] = va.w;
            float4 vb = *(const float4*)(Wp + (size_t)row * I_ + k0 + col4 * 4);
            Bs[(col4 * 4 + 0) * LDS + row] = vb.x;
            Bs[(col4 * 4 + 1) * LDS + row] = vb.y;
            Bs[(col4 * 4 + 2) * LDS + row] = vb.z;
            Bs[(col4 * 4 + 3) * LDS + row] = vb.w;
        }
        __syncthreads();

        #pragma unroll
        for (int k = 0; k < BK; k++) {
            float a[TM], bv[TN];
            const float4* ap = (const float4*)&As[k * LDS + ty * TM];
            float4 a0 = ap[0], a1 = ap[1];
            a[0]=a0.x; a[1]=a0.y; a[2]=a0.z; a[3]=a0.w;
            a[4]=a1.x; a[5]=a1.y; a[6]=a1.z; a[7]=a1.w;
            float4 b0 = *(const float4*)&Bs[k * LDS + tx * TN];
            bv[0]=b0.x; bv[1]=b0.y; bv[2]=b0.z; bv[3]=b0.w;

            #pragma unroll
            for (int i = 0; i < TM; i++) {
                #pragma unroll
                for (int j = 0; j < TN; j++) {
                    // TwoProd: p + e == a*b exactly
                    float p = __fmul_rn(a[i], bv[j]);
                    float e = __fmaf_rn(a[i], bv[j], -p);
                    // TwoSum: t + err == s + p exactly
                    float t  = __fadd_rn(s[i][j], p);
                    float z  = __fsub_rn(t, s[i][j]);
                    float err = __fadd_rn(__fsub_rn(s[i][j], __fsub_rn(t, z)),
                                          __fsub_rn(p, z));
                    s[i][j] = t;
                    c[i][j] = __fadd_rn(c[i][j], __fadd_rn(err, e));
                }
            }
        }
        __syncthreads();
    }

    // Epilogue: fold compensation, add bias, store.
    #pragma unroll
    for (int i = 0; i < TM; i++) {
        size_t row = (size_t)by * BM + ty * TM + i;
        float* outp = proj + row * H_ + bx * BN + tx * TN;
        float r[TN];
        #pragma unroll
        for (int j = 0; j < TN; j++) {
            float v = __fadd_rn(s[i][j], c[i][j]);
            r[j] = __fadd_rn(v, bias[bx * BN + tx * TN + j]);
        }
        *(float4*)outp = make_float4(r[0], r[1], r[2], r[3]);
    }
}

// ---------------------------------------------------------------------------
// Kernel B: LIF scan over T. One thread per (b,h). Coalesced along h.
// Unfused mul+add to match XLA's separate multiply/add HLO ops.
// out layout: spikes [B,T,H] then h_final [B,H]
// ---------------------------------------------------------------------------
__global__ __launch_bounds__(256)
void lif_scan_kernel(const float* __restrict__ proj,
                     float* __restrict__ out)
{
    int idx = blockIdx.x * blockDim.x + threadIdx.x;  // 0 .. B*H-1
    if (idx >= B_ * H_) return;
    int b = idx / H_;
    int h = idx % H_;

    const size_t base = (size_t)b * T_ * H_ + h;
    float hstate = 0.0f;

    #pragma unroll 4
    for (int t = 0; t < T_; t++) {
        float p = proj[base + (size_t)t * H_];
        hstate = __fadd_rn(__fmul_rn(0.9f, hstate), p);
        float sp = (hstate >= 1.0f) ? 1.0f : 0.0f;
        out[base + (size_t)t * H_] = sp;
        hstate = __fmul_rn(hstate, __fsub_rn(1.0f, sp));
    }

    out[(size_t)B_ * T_ * H_ + (size_t)b * H_ + h] = hstate;
}

// ---------------------------------------------------------------------------
extern "C" void kernel_launch(void* const* d_in, const int* in_sizes, int n_in,
                              void* d_out, int out_size)
{
    const float* X    = (const float*)d_in[0];   // [256,100,2048]
    const float* W    = (const float*)d_in[1];   // [2048,2048]
    const float* bias = (const float*)d_in[2];   // [2048]
    float* out = (float*)d_out;

    float* proj;
    cudaGetSymbolAddress((void**)&proj, g_proj);

    dim3 ggrid(H_ / BN, M_ / BM);   // (16, 200)
    lif_gemm_eft_kernel<<<ggrid, NTHREADS>>>(X, W, bias, proj);

    int nthreads = B_ * H_;
    lif_scan_kernel<<<(nthreads + 255) / 256, 256>>>(proj, out);
}